// round 11
// baseline (speedup 1.0000x reference)
#include <cuda_runtime.h>

// D2Q9 LBM single step — element-parallel collide into smem with COALESCED f
// loads and incremental (div-free) index stepping, then smem stream-gather +
// bounce-back + macro lift.
//   f    [2048,2048,9]  f32
//   rho  [2048,2048]    f32
//   u    [2048,2048,2]  f32 (float2)
//   mask [2048,2048]    bool, dtype unknown (u8/i32/f32) -> runtime detection
//   out  [2048,2048,12] f32  (f_new[9], rho_new, ux, uy)
//
// jnp.roll(a, shift=e) => new[x,y] = old[x-ex, y-ey] (periodic &2047).

#define NXg 2048
#define NYg 2048
#define WRAP(v) ((v) & 2047)

#define TW 64               // tile width  (y, contiguous)
#define TH 8                // tile height (x)
#define HW (TW + 2)         // 66
#define HH (TH + 2)         // 10
#define HCELLS (HW * HH)    // 660
#define HELEMS (HCELLS * 9) // 5940
#define NITER  ((HELEMS + 255) / 256)          // 24
#define TAIL   (HELEMS - (NITER - 1) * 256)    // 52

// ---- mask dtype detection (device globals zero-init; atomicOr idempotent) ----
__device__ unsigned int g_byte_flags[4];

__global__ void detect_mask_kernel(const uint4* __restrict__ mask_v) {
    // Scan first 256 KB (smallest candidate buffer is 4 MB; ~65k cells seen).
    const int nvec = (256 * 1024) / 16;
    unsigned int loc0 = 0, loc1 = 0, loc2 = 0, loc3 = 0;
    for (int i = blockIdx.x * blockDim.x + threadIdx.x; i < nvec;
         i += gridDim.x * blockDim.x) {
        uint4 v = mask_v[i];
        unsigned int w = v.x | v.y | v.z | v.w;
        loc0 |= (w & 0x000000FFu);
        loc1 |= (w & 0x0000FF00u);
        loc2 |= (w & 0x00FF0000u);
        loc3 |= (w & 0xFF000000u);
    }
    if (loc0) atomicOr(&g_byte_flags[0], 1u);
    if (loc1) atomicOr(&g_byte_flags[1], 1u);
    if (loc2) atomicOr(&g_byte_flags[2], 1u);
    if (loc3) atomicOr(&g_byte_flags[3], 1u);
}

__global__ __launch_bounds__(256, 4)
void lbm_step_kernel(const float*  __restrict__ f,
                     const float*  __restrict__ rho,
                     const float2* __restrict__ u,
                     const void*   __restrict__ mask,
                     float* __restrict__ out)
{
    __shared__ float fs[HELEMS];   // f_star tile+halo, flat [cell][i], 23.8 KB

    const int tid = threadIdx.x;
    const int Y0  = blockIdx.x * TW;
    const int X0  = blockIdx.y * TH;

    // Resolve mask dtype from detection flags (uniform loads, L2 broadcast)
    const bool b0  = g_byte_flags[0] != 0;
    const bool b1  = g_byte_flags[1] != 0;
    const bool b23 = (g_byte_flags[2] | g_byte_flags[3]) != 0;
    int mode;
    if (b1 || (b0 && b23)) mode = 0;       // 1-byte mask
    else if (b0)           mode = 1;       // int32
    else if (b23)          mode = 2;       // float32
    else                   mode = 0;       // no solids in window: any read works

    // Early mask loads for this thread's 2 output cells (latency hidden by A)
    const int ly  = tid & (TW - 1);        // 0..63
    const int lx0 = tid >> 6;              // 0..3 (second cell at lx0+4)
    bool solid[2];
    #pragma unroll
    for (int cp = 0; cp < 2; cp++) {
        const unsigned cell = (unsigned)(X0 + lx0 + 4 * cp) * NYg + (Y0 + ly);
        if (mode == 0)      solid[cp] = ((const unsigned char*)mask)[cell] != 0;
        else if (mode == 1) solid[cp] = ((const int*)mask)[cell] != 0;
        else                solid[cp] = ((const float*)mask)[cell] != 0.0f;
    }

    const float INV_TAU = 1.0f / 0.6f;

    // ---- Phase A: element-parallel collide -> smem; coalesced f loads;
    //      index math done incrementally (no div/mod in the loop).
    // n = cell*9 + i over tile+halo; per +256: i += 4 (carry), hy += 28/29 (carry)
    unsigned c0 = (unsigned)tid / 9u;          // one-time (mul-shift)
    unsigned i  = (unsigned)tid - c0 * 9u;
    unsigned h  = c0 / (unsigned)HW;           // one-time
    unsigned hy = c0 - h * (unsigned)HW;

    #pragma unroll
    for (int k = 0; k < NITER; k++) {
        if (k < NITER - 1 || tid < TAIL) {
            const int n  = k * 256 + tid;
            const int gx = WRAP(X0 + (int)h - 1);
            const int gy = WRAP(Y0 + (int)hy - 1);
            const unsigned gc = (unsigned)gx * NYg + (unsigned)gy;

            const float  fv = f[gc * 9u + i];
            const float  r  = rho[gc];            // 9-thread broadcast
            const float2 uv = u[gc];

            // ex=+1 at i in {1,5,8}=0x122, -1 at {3,6,7}=0x0C8
            // ey=+1 at i in {2,5,6}=0x064, -1 at {4,7,8}=0x190
            const float ex = (float)((0x122u >> i) & 1u) - (float)((0x0C8u >> i) & 1u);
            const float ey = (float)((0x064u >> i) & 1u) - (float)((0x190u >> i) & 1u);
            const float w  = (i == 0u) ? (4.0f / 9.0f)
                                       : ((i < 5u) ? (1.0f / 9.0f) : (1.0f / 36.0f));

            const float eu  = ex * uv.x + ey * uv.y;
            const float usq = uv.x * uv.x + uv.y * uv.y;
            const float feq = w * r * (1.0f + 3.0f * eu + 4.5f * eu * eu - 1.5f * usq);
            fs[n] = fv - (fv - feq) * INV_TAU;
        }
        // advance (256 = 28*9 + 4): i += 4 mod 9 w/ carry into cell count
        i += 4u;
        unsigned inc = 28u;
        if (i >= 9u) { i -= 9u; inc = 29u; }
        hy += inc;                       // hy advances < HW per step
        if (hy >= (unsigned)HW) { hy -= (unsigned)HW; h += 1u; }
    }
    __syncthreads();

    // ---- Phase B: smem gather + bounce-back + macro lift + float4 stores ----
    const int EXq[9]  = {0, 1, 0, -1,  0, 1, -1, -1,  1};
    const int EYq[9]  = {0, 0, 1,  0, -1, 1,  1, -1, -1};
    const int OPPq[9] = {0, 3, 4, 1, 2, 7, 8, 5, 6};

    #pragma unroll
    for (int cp = 0; cp < 2; cp++) {
        const int lx = lx0 + 4 * cp;
        const unsigned cell = (unsigned)(X0 + lx) * NYg + (Y0 + ly);

        float fn[9];
        if (solid[cp]) {
            const int base = ((lx + 1) * HW + (ly + 1)) * 9;
            #pragma unroll
            for (int q = 0; q < 9; q++) fn[q] = fs[base + OPPq[q]];
        } else {
            #pragma unroll
            for (int q = 0; q < 9; q++)
                fn[q] = fs[((lx + 1 - EXq[q]) * HW + (ly + 1 - EYq[q])) * 9 + q];
        }

        float rn = 0.0f;
        #pragma unroll
        for (int q = 0; q < 9; q++) rn += fn[q];
        const float uxn = (fn[1] - fn[3]) + (fn[5] - fn[6]) + (fn[8] - fn[7]);
        const float uyn = (fn[2] - fn[4]) + (fn[5] + fn[6]) - (fn[7] + fn[8]);
        const float inv_rn = 1.0f / rn;

        float4* op = reinterpret_cast<float4*>(out + (size_t)cell * 12);
        op[0] = make_float4(fn[0], fn[1], fn[2], fn[3]);
        op[1] = make_float4(fn[4], fn[5], fn[6], fn[7]);
        op[2] = make_float4(fn[8], rn, uxn * inv_rn, uyn * inv_rn);
    }
}

extern "C" void kernel_launch(void* const* d_in, const int* in_sizes, int n_in,
                              void* d_out, int out_size)
{
    const float*  f    = (const float*)d_in[0];
    const float*  rho  = (const float*)d_in[1];
    const float2* u    = (const float2*)d_in[2];
    const void*   mask = d_in[3];
    float*        out  = (float*)d_out;

    detect_mask_kernel<<<32, 256>>>((const uint4*)mask);

    dim3 block(256);
    dim3 grid(NYg / TW, NXg / TH);   // 32 x 256 = 8192 CTAs
    lbm_step_kernel<<<grid, block>>>(f, rho, u, mask, out);
}

// round 12
// speedup vs baseline: 2.0174x; 2.0174x over previous
#include <cuda_runtime.h>

// D2Q9 LBM single step — smem-staged f (bulk uint4 copy), in-place collide,
// smem stream-gather + bounce-back + macro lift.
//   f    [2048,2048,9]  f32
//   rho  [2048,2048]    f32
//   u    [2048,2048,2]  f32 (float2)
//   mask [2048,2048]    bool, dtype unknown (u8/i32/f32) -> runtime detection
//   out  [2048,2048,12] f32  (f_new[9], rho_new, ux, uy)
//
// jnp.roll(a, shift=e) => new[x,y] = old[x-ex, y-ey] (periodic &2047).

#define NXg 2048
#define NYg 2048
#define WRAP(v) ((v) & 2047)

#define TW 64                 // tile width (y, contiguous)
#define TH 8                  // tile height (x)
#define NROWS (TH + 2)        // 10 halo rows
// smem row layout (floats): [ inner 64 cells *9 = 576 | hy=0 edge: 9 | hy=65 edge: 9 ] + pad
#define RSTRIDE 596           // 594 + 2 pad (keeps %4==0 for aligned uint4 stores)
#define EDGE_LO 576           // offset of hy==0 cell within row
#define EDGE_HI 585           // offset of hy==65 cell within row
#define ROW_U4 144            // 576 floats / 4 per inner span
#define NU4 (NROWS * ROW_U4)  // 1440 uint4 copies per CTA

// ---- mask dtype detection (device globals zero-init; atomicOr idempotent) ----
__device__ unsigned int g_byte_flags[4];

__global__ void detect_mask_kernel(const uint4* __restrict__ mask_v) {
    const int nvec = (256 * 1024) / 16;   // scan first 256 KB
    unsigned int loc0 = 0, loc1 = 0, loc2 = 0, loc3 = 0;
    for (int i = blockIdx.x * blockDim.x + threadIdx.x; i < nvec;
         i += gridDim.x * blockDim.x) {
        uint4 v = mask_v[i];
        unsigned int w = v.x | v.y | v.z | v.w;
        loc0 |= (w & 0x000000FFu);
        loc1 |= (w & 0x0000FF00u);
        loc2 |= (w & 0x00FF0000u);
        loc3 |= (w & 0xFF000000u);
    }
    if (loc0) atomicOr(&g_byte_flags[0], 1u);
    if (loc1) atomicOr(&g_byte_flags[1], 1u);
    if (loc2) atomicOr(&g_byte_flags[2], 1u);
    if (loc3) atomicOr(&g_byte_flags[3], 1u);
}

__global__ __launch_bounds__(256, 4)
void lbm_step_kernel(const float*  __restrict__ f,
                     const float*  __restrict__ rho,
                     const float2* __restrict__ u,
                     const void*   __restrict__ mask,
                     float* __restrict__ out)
{
    __shared__ float fs[NROWS * RSTRIDE];   // 5960 floats = 23.84 KB

    const int tid = threadIdx.x;
    const int Y0  = blockIdx.x * TW;
    const int X0  = blockIdx.y * TH;

    // Resolve mask dtype (uniform loads)
    const bool b0  = g_byte_flags[0] != 0;
    const bool b1  = g_byte_flags[1] != 0;
    const bool b23 = (g_byte_flags[2] | g_byte_flags[3]) != 0;
    int mode;
    if (b1 || (b0 && b23)) mode = 0;
    else if (b0)           mode = 1;
    else if (b23)          mode = 2;
    else                   mode = 0;

    // Early mask loads for this thread's 2 output cells
    const int ly  = tid & (TW - 1);
    const int lx0 = tid >> 6;
    bool solid[2];
    #pragma unroll
    for (int cp = 0; cp < 2; cp++) {
        const unsigned cell = (unsigned)(X0 + lx0 + 4 * cp) * NYg + (Y0 + ly);
        if (mode == 0)      solid[cp] = ((const unsigned char*)mask)[cell] != 0;
        else if (mode == 1) solid[cp] = ((const int*)mask)[cell] != 0;
        else                solid[cp] = ((const float*)mask)[cell] != 0.0f;
    }

    // ---- Phase 1: bulk copy inner f spans (aligned uint4, coalesced) ----
    // Row r covers gx = WRAP(X0+r-1), cells gy in [Y0, Y0+64): 576 floats, 16B-aligned.
    #pragma unroll
    for (int k = 0; k < 6; k++) {
        const int idx = k * 256 + tid;
        if (k < 5 || idx < NU4) {
            const int r   = idx / ROW_U4;            // constant div -> mul.hi
            const int col = idx - r * ROW_U4;
            const int gx  = WRAP(X0 + r - 1);
            const size_t basef = ((size_t)gx * NYg + Y0) * 9;   // %4 == 0
            const uint4 v = *reinterpret_cast<const uint4*>(f + basef + col * 4);
            *reinterpret_cast<uint4*>(&fs[r * RSTRIDE + col * 4]) = v;
        }
    }
    __syncthreads();

    const float INV_TAU = 1.0f / 0.6f;
    const int   EXq[9]  = {0, 1, 0, -1,  0, 1, -1, -1,  1};
    const int   EYq[9]  = {0, 0, 1,  0, -1, 1,  1, -1, -1};
    const float Wq[9]   = {4.0f/9.0f,
                           1.0f/9.0f, 1.0f/9.0f, 1.0f/9.0f, 1.0f/9.0f,
                           1.0f/36.0f, 1.0f/36.0f, 1.0f/36.0f, 1.0f/36.0f};
    const int   OPPq[9] = {0, 3, 4, 1, 2, 7, 8, 5, 6};

    // ---- Phase 2a: collide in place (inner cells from smem, edges from gmem) ----
    // inner: 640 cells, ids 0..639: r=c>>6, cy=c&63 (no divisions)
    #pragma unroll
    for (int k = 0; k < 3; k++) {
        const int c = k * 256 + tid;
        if (c < 640) {
            const int r  = c >> 6;
            const int cy = c & 63;
            const int gx = WRAP(X0 + r - 1);
            const unsigned gc = (unsigned)gx * NYg + (Y0 + cy);
            const float  rr = rho[gc];
            const float2 uv = u[gc];
            const float  usq = uv.x * uv.x + uv.y * uv.y;
            const int base = r * RSTRIDE + cy * 9;
            #pragma unroll
            for (int q = 0; q < 9; q++) {
                const float fv = fs[base + q];
                const float eu = (float)EXq[q] * uv.x + (float)EYq[q] * uv.y;
                const float feq = Wq[q] * rr *
                                  (1.0f + 3.0f * eu + 4.5f * eu * eu - 1.5f * usq);
                fs[base + q] = fv - (fv - feq) * INV_TAU;
            }
        } else if (c < 660) {
            // edge cells: e = c-640 in 0..19 -> row r=e>>1, side=e&1 (hy 0 or 65)
            const int e    = c - 640;
            const int r    = e >> 1;
            const int side = e & 1;
            const int gx = WRAP(X0 + r - 1);
            const int gy = WRAP(side ? (Y0 + TW) : (Y0 - 1));
            const unsigned gc = (unsigned)gx * NYg + gy;
            const float  rr = rho[gc];
            const float2 uv = u[gc];
            const float  usq = uv.x * uv.x + uv.y * uv.y;
            const int base = r * RSTRIDE + (side ? EDGE_HI : EDGE_LO);
            const float* fc = f + (size_t)gc * 9;
            #pragma unroll
            for (int q = 0; q < 9; q++) {
                const float fv = fc[q];
                const float eu = (float)EXq[q] * uv.x + (float)EYq[q] * uv.y;
                const float feq = Wq[q] * rr *
                                  (1.0f + 3.0f * eu + 4.5f * eu * eu - 1.5f * usq);
                fs[base + q] = fv - (fv - feq) * INV_TAU;
            }
        }
    }
    __syncthreads();

    // ---- Phase 2b: stream-gather from smem + bounce-back + macro + stores ----
    // y-offset within a row, per EY class (edge slots handled by select):
    const int offY_p = (ly == 0)      ? EDGE_LO : (ly - 1) * 9;  // EY=+1: hy=ly
    const int offY_0 = ly * 9;                                    // EY= 0: hy=ly+1
    const int offY_m = (ly == TW - 1) ? EDGE_HI : (ly + 1) * 9;  // EY=-1: hy=ly+2
    const int offY[3] = {offY_p, offY_0, offY_m};                 // index 1-EY

    #pragma unroll
    for (int cp = 0; cp < 2; cp++) {
        const int lx = lx0 + 4 * cp;
        const unsigned cell = (unsigned)(X0 + lx) * NYg + (Y0 + ly);

        float fn[9];
        if (solid[cp]) {
            const int base = (lx + 1) * RSTRIDE + ly * 9;
            #pragma unroll
            for (int q = 0; q < 9; q++) fn[q] = fs[base + OPPq[q]];
        } else {
            #pragma unroll
            for (int q = 0; q < 9; q++)
                fn[q] = fs[(lx + 1 - EXq[q]) * RSTRIDE + offY[1 - EYq[q]] + q];
        }

        float rn = 0.0f;
        #pragma unroll
        for (int q = 0; q < 9; q++) rn += fn[q];
        const float uxn = (fn[1] - fn[3]) + (fn[5] - fn[6]) + (fn[8] - fn[7]);
        const float uyn = (fn[2] - fn[4]) + (fn[5] + fn[6]) - (fn[7] + fn[8]);
        const float inv_rn = 1.0f / rn;

        float4* op = reinterpret_cast<float4*>(out + (size_t)cell * 12);
        op[0] = make_float4(fn[0], fn[1], fn[2], fn[3]);
        op[1] = make_float4(fn[4], fn[5], fn[6], fn[7]);
        op[2] = make_float4(fn[8], rn, uxn * inv_rn, uyn * inv_rn);
    }
}

extern "C" void kernel_launch(void* const* d_in, const int* in_sizes, int n_in,
                              void* d_out, int out_size)
{
    const float*  f    = (const float*)d_in[0];
    const float*  rho  = (const float*)d_in[1];
    const float2* u    = (const float2*)d_in[2];
    const void*   mask = d_in[3];
    float*        out  = (float*)d_out;

    detect_mask_kernel<<<32, 256>>>((const uint4*)mask);

    dim3 block(256);
    dim3 grid(NYg / TW, NXg / TH);   // 32 x 256 = 8192 CTAs
    lbm_step_kernel<<<grid, block>>>(f, rho, u, mask, out);
}